// round 14
// baseline (speedup 1.0000x reference)
#include <cuda_runtime.h>
#include <cstdint>

#define NB 16
#define NT 2048
#define ND 512
#define TBLK 8             // timesteps per alphas tile
#define NTILE (NT / TBLK)  // 256 tiles per batch
#define HTILE (NTILE / 2)  // 128 tile-pairs per batch
#define CH 32              // pass-2 chunk length (timesteps)
#define NCH (NT / CH)      // 64 chunks

// ---------------- scratch (device globals; no allocation allowed) ----------
__device__ __align__(16) float g_aT4[NT * NB];   // alphas, layout [t/4][b][4]
__device__ __align__(16) float g_Wt[NB * NT];    // per-step weight (cur), exact
__device__ __align__(16) float2 g_fire[NB * NT]; // per fire: (t as int bits, rem)
__device__ float g_integ0[NCH * NB];             // integ at chunk start
__device__ int   g_nf0[NCH * NB];                // fire count before chunk
__device__ int   g_nf[NB];                       // total fire count per batch

// set.ge.f32 -> 1.0f/0.0f without a predicate on the dependency chain
__device__ __forceinline__ float fset_ge1(float s) {
    float r;
    asm("set.ge.f32.f32 %0, %1, 0f3F800000;" : "=f"(r) : "f"(s));
    return r;
}

__device__ __forceinline__ uint32_t smem_u32(const void* p) {
    uint32_t a;
    asm("{ .reg .u64 t; cvta.to.shared.u64 t, %1; cvt.u32.u64 %0, t; }"
        : "=r"(a) : "l"(p));
    return a;
}

__device__ __forceinline__ void mbar_wait0(uint32_t mbar) {
    asm volatile(
        "{\n\t.reg .pred P1;\n\t"
        "W%=:\n\t"
        "mbarrier.try_wait.parity.acquire.cta.shared::cta.b64 P1, [%0], 0, 0x989680;\n\t"
        "@!P1 bra W%=;\n\t}"
        :: "r"(mbar) : "memory");
}

// ---------------- kernel A: alphas, double-buffered 2-tile CTA --------------
// Block handles tiles x and x+HTILE (far apart; no row sharing). BOTH TMAs
// issue up front; tile B is in flight while tile A computes. Weights load
// once for both tiles (same fixed d-slice per thread). Per-tile compute is
// byte-identical to r13 => bit-exact.
__global__ __launch_bounds__(128, 5)
void alphas_kernel(const float* __restrict__ hidden,
                   const float* __restrict__ conv_w,
                   const float* __restrict__ conv_b,
                   const float* __restrict__ lin_w,
                   const float* __restrict__ lin_b,
                   float* __restrict__ alphas) {
    __shared__ __align__(128) float sh[2][(TBLK + 2) * ND];   // 2 x 20KB
    __shared__ __align__(8) unsigned long long mbar[2];
    __shared__ float red[2][4][TBLK];

    const int b = blockIdx.y;
    const int x = blockIdx.x;

    if (threadIdx.x == 0) {
#pragma unroll
        for (int p = 0; p < 2; p++) {
            const int t0     = (x + p * HTILE) * TBLK;
            const int gstart = (t0 == 0) ? 0 : t0 - 1;
            const int gend   = (t0 + TBLK < NT) ? t0 + TBLK : NT - 1;
            const int nrows  = gend - gstart + 1;           // 9 or 10
            const int dstrow = (t0 == 0) ? 1 : 0;
            const uint32_t mb = smem_u32(&mbar[p]);
            asm volatile("mbarrier.init.shared.b64 [%0], 1;" :: "r"(mb) : "memory");
            const uint32_t bytes = nrows * ND * 4;
            const uint32_t dst   = smem_u32(sh[p]) + dstrow * ND * 4;
            const float* src = hidden + (size_t)b * NT * ND + (size_t)gstart * ND;
            asm volatile("mbarrier.arrive.expect_tx.shared.b64 _, [%0], %1;"
                         :: "r"(mb), "r"(bytes) : "memory");
            asm volatile(
                "cp.async.bulk.shared::cta.global.mbarrier::complete_tx::bytes "
                "[%0], [%1], %2, [%3];"
                :: "r"(dst), "l"(src), "r"(bytes), "r"(mb) : "memory");
        }
    }

    // weight preload (shared by both tiles) — overlaps the TMA flights
    const int d = threadIdx.x * 4;
    const float4 c0 = *reinterpret_cast<const float4*>(&conv_w[d * 3]);
    const float4 c1 = *reinterpret_cast<const float4*>(&conv_w[d * 3 + 4]);
    const float4 c2 = *reinterpret_cast<const float4*>(&conv_w[d * 3 + 8]);
    const float4 w0 = make_float4(c0.x, c0.w, c1.z, c2.y);
    const float4 w1 = make_float4(c0.y + 1.f, c1.x + 1.f, c1.w + 1.f, c2.z + 1.f);
    const float4 w2 = make_float4(c0.z, c1.y, c2.x, c2.w);
    const float4 cb4 = *reinterpret_cast<const float4*>(&conv_b[d]);
    const float4 lw  = *reinterpret_cast<const float4*>(&lin_w[d]);
    const float lb   = __ldg(lin_b);

    // pad rows (regions the TMAs do not write) — also overlap the flights
    if (x == 0) {                   // tile0 t0==0: pad row 0 of sh[0]
        *reinterpret_cast<float4*>(&sh[0][d]) = make_float4(0.f, 0.f, 0.f, 0.f);
    }
    if (x == HTILE - 1) {           // tile1 ends at NT: pad row TBLK+1 of sh[1]
        *reinterpret_cast<float4*>(&sh[1][(TBLK + 1) * ND + d]) =
            make_float4(0.f, 0.f, 0.f, 0.f);
    }

    __syncthreads();        // publish mbar inits + pad rows

    const int warp = threadIdx.x >> 5;
    const int lane = threadIdx.x & 31;

#pragma unroll
    for (int p = 0; p < 2; p++) {
        const int t0 = (x + p * HTILE) * TBLK;
        mbar_wait0(smem_u32(&mbar[p]));

        // rolling 3-tap window over 8 timesteps, fixed d-slice
        float acc[TBLK];
        float4 hm = *reinterpret_cast<const float4*>(&sh[p][d]);
        float4 hc = *reinterpret_cast<const float4*>(&sh[p][ND + d]);
#pragma unroll
        for (int i = 0; i < TBLK; i++) {
            const float4 hp =
                *reinterpret_cast<const float4*>(&sh[p][(i + 2) * ND + d]);
            float a = 0.f, v;
            v = fmaf(hm.x, w0.x, fmaf(hc.x, w1.x, fmaf(hp.x, w2.x, cb4.x)));
            a = fmaf(fmaxf(v, 0.f), lw.x, a);
            v = fmaf(hm.y, w0.y, fmaf(hc.y, w1.y, fmaf(hp.y, w2.y, cb4.y)));
            a = fmaf(fmaxf(v, 0.f), lw.y, a);
            v = fmaf(hm.z, w0.z, fmaf(hc.z, w1.z, fmaf(hp.z, w2.z, cb4.z)));
            a = fmaf(fmaxf(v, 0.f), lw.z, a);
            v = fmaf(hm.w, w0.w, fmaf(hc.w, w1.w, fmaf(hp.w, w2.w, cb4.w)));
            a = fmaf(fmaxf(v, 0.f), lw.w, a);
            acc[i] = a;
            hm = hc; hc = hp;
        }

#pragma unroll
        for (int o = 16; o > 0; o >>= 1) {
#pragma unroll
            for (int i = 0; i < TBLK; i++)
                acc[i] += __shfl_xor_sync(0xffffffffu, acc[i], o);
        }
        if (lane == 0) {
#pragma unroll
            for (int i = 0; i < TBLK; i++) red[p][warp][i] = acc[i];
        }
    }
    __syncthreads();

    if (threadIdx.x < 2 * TBLK) {
        const int p = threadIdx.x >> 3;          // 0 or 1
        const int i = threadIdx.x & 7;
        const int t = (x + p * HTILE) * TBLK + i;
        const float s =
            ((red[p][0][i] + red[p][1][i]) + (red[p][2][i] + red[p][3][i])) + lb;
        const float sg = 1.0f / (1.0f + __expf(-s));
        alphas[b * NT + t] = sg;
        g_aT4[((t >> 2) * NB + b) * 4 + (t & 3)] = sg;
    }
}

// ---------------- kernel B1: minimal sequential chain (pass 1) -------------
// (r7/r11-proven) Chain: FADD -> FSET (predicate-free) -> FADD = 12 cyc/step.
__global__ void scan_pass1(float* __restrict__ token_num) {
    const int b = threadIdx.x;
    if (b >= NB) return;

    const float4* ap = reinterpret_cast<const float4*>(g_aT4) + b;
    float4 buf_cur[8], buf_nxt[8];
#pragma unroll
    for (int k = 0; k < 8; k++) buf_cur[k] = ap[k * NB];

    float integ = 0.f, tn = 0.f, nfF = 0.f;

    for (int t0 = 0; t0 < NT; t0 += CH) {
        g_integ0[(t0 >> 5) * NB + b] = integ;
        g_nf0[(t0 >> 5) * NB + b]   = (int)nfF;
        if (t0 + CH < NT) {
#pragma unroll
            for (int k = 0; k < 8; k++) buf_nxt[k] = ap[((t0 >> 2) + 8 + k) * NB];
        }
#pragma unroll
        for (int k = 0; k < 8; k++) {
            float a4[4] = {buf_cur[k].x, buf_cur[k].y, buf_cur[k].z, buf_cur[k].w};
#pragma unroll
            for (int i = 0; i < 4; i++) {
                const float a   = a4[i];
                const float s   = integ + a;     // chain: FADD
                const float sel = fset_ge1(s);   // chain: FSET (1.0/0.0, no pred)
                nfF += sel;                      // off-chain
                tn  += a;                        // off-chain
                integ = s - sel;                 // chain: FADD (== s-1.0f at fires)
            }
        }
#pragma unroll
        for (int k = 0; k < 8; k++) buf_cur[k] = buf_nxt[k];
    }
    g_nf[b] = (int)nfF;
    token_num[b] = tn;
}

// ---------------- kernel B2: parallel chunk replay (pass 2) ----------------
__global__ void scan_pass2(float* __restrict__ fires) {
    const int c = blockIdx.x;
    const int b = threadIdx.x;
    if (b >= NB) return;

    float integ = g_integ0[c * NB + b];
    int nf      = g_nf0[c * NB + b];
    const int tbase = c * CH;
    const float4* ap = reinterpret_cast<const float4*>(g_aT4) + b;
    float*  fb = fires + b * NT;
    float*  wb = g_Wt + b * NT;
    float2* pb = g_fire + b * NT;

#pragma unroll
    for (int k = 0; k < 8; k++) {
        const float4 av = ap[((tbase >> 2) + k) * NB];
        float a4[4] = {av.x, av.y, av.z, av.w};
        float4 fout, wout;
#pragma unroll
        for (int i = 0; i < 4; i++) {
            const float a    = a4[i];
            const float dist = 1.0f - integ;
            const float s    = integ + a;
            const bool fire  = (s >= 1.0f);
            const float cur  = fire ? dist : a;
            ((float*)&fout)[i] = s;
            ((float*)&wout)[i] = cur;
            const float rem = a - cur;
            if (fire) pb[nf] = make_float2(__int_as_float(tbase + k * 4 + i), rem);
            nf += fire ? 1 : 0;
            integ = fire ? (s - 1.0f) : s;
        }
        const int t = tbase + k * 4;
        *reinterpret_cast<float4*>(fb + t) = fout;
        *reinterpret_cast<float4*>(wb + t) = wout;
    }
}

// ---------------- kernel C: segmented gather, hot-first + 4-wide MLP --------
// r = ML-1-bid (hot rows first). Inner loop processes 4 rows per iteration
// with per-row predicates: disabled rows contribute fma(0, 0, acc) == acc
// exactly, and accumulation order over live rows is unchanged => bit-exact.
__global__ void gather_kernel(const float* __restrict__ hidden,
                              float* __restrict__ acoustic, int ML) {
    const int r = gridDim.x - 1 - blockIdx.x;       // hot rows first
    const int b = blockIdx.y;
    const int d = threadIdx.x * 4;

    float4 acc = make_float4(0.f, 0.f, 0.f, 0.f);
    if (r < g_nf[b]) {
        const float* hb = hidden + (size_t)b * NT * ND + d;
        const float* wb = g_Wt + b * NT;
        const float2 fc = g_fire[b * NT + r];               // parallel loads
        const float2 fp = g_fire[b * NT + (r > 0 ? r - 1 : 0)];
        const int end   = __float_as_int(fc.x);
        int start = 0;
        if (r > 0) {
            const int ps    = __float_as_int(fp.x);
            const float rem = fp.y;
            const float4 h  = *reinterpret_cast<const float4*>(hb + (size_t)ps * ND);
            acc.x = rem * h.x; acc.y = rem * h.y;
            acc.z = rem * h.z; acc.w = rem * h.w;
            start = ps + 1;
        }
        const float4 z = make_float4(0.f, 0.f, 0.f, 0.f);
        for (int tt = start; tt <= end; tt += 4) {
            const bool q1 = (tt + 1 <= end), q2 = (tt + 2 <= end), q3 = (tt + 3 <= end);
            const float w0 = wb[tt];
            const float w1 = q1 ? wb[tt + 1] : 0.f;
            const float w2 = q2 ? wb[tt + 2] : 0.f;
            const float w3 = q3 ? wb[tt + 3] : 0.f;
            const float4 h0 = *reinterpret_cast<const float4*>(hb + (size_t)tt * ND);
            const float4 h1 = q1 ? *reinterpret_cast<const float4*>(hb + (size_t)(tt + 1) * ND) : z;
            const float4 h2 = q2 ? *reinterpret_cast<const float4*>(hb + (size_t)(tt + 2) * ND) : z;
            const float4 h3 = q3 ? *reinterpret_cast<const float4*>(hb + (size_t)(tt + 3) * ND) : z;
            acc.x = fmaf(w0, h0.x, acc.x); acc.y = fmaf(w0, h0.y, acc.y);
            acc.z = fmaf(w0, h0.z, acc.z); acc.w = fmaf(w0, h0.w, acc.w);
            acc.x = fmaf(w1, h1.x, acc.x); acc.y = fmaf(w1, h1.y, acc.y);
            acc.z = fmaf(w1, h1.z, acc.z); acc.w = fmaf(w1, h1.w, acc.w);
            acc.x = fmaf(w2, h2.x, acc.x); acc.y = fmaf(w2, h2.y, acc.y);
            acc.z = fmaf(w2, h2.z, acc.z); acc.w = fmaf(w2, h2.w, acc.w);
            acc.x = fmaf(w3, h3.x, acc.x); acc.y = fmaf(w3, h3.y, acc.y);
            acc.z = fmaf(w3, h3.z, acc.z); acc.w = fmaf(w3, h3.w, acc.w);
        }
    }
    // r >= nf -> zeros (reference zero-pads); also overwrites 0xAA poison.
    *reinterpret_cast<float4*>(&acoustic[((size_t)b * ML + r) * ND + d]) = acc;
}

// ---------------- launch ----------------------------------------------------
extern "C" void kernel_launch(void* const* d_in, const int* in_sizes, int n_in,
                              void* d_out, int out_size) {
    const float* hidden = (const float*)d_in[0];
    const float* conv_w = (const float*)d_in[1];
    const float* conv_b = (const float*)d_in[2];
    const float* lin_w  = (const float*)d_in[3];
    const float* lin_b  = (const float*)d_in[4];
    float* out = (float*)d_out;

    // out = concat(acoustic[B,ML,D], token_num[B], alphas[B,T], fires[B,T])
    const int ML = (out_size - NB - 2 * NB * NT) / (NB * ND);
    float* acoustic  = out;
    float* token_num = out + (size_t)NB * ML * ND;
    float* alphas    = token_num + NB;
    float* fires     = alphas + NB * NT;

    alphas_kernel<<<dim3(HTILE, NB), 128>>>(hidden, conv_w, conv_b,
                                            lin_w, lin_b, alphas);
    scan_pass1<<<1, 32>>>(token_num);
    scan_pass2<<<NCH, 32>>>(fires);
    if (ML > 0) gather_kernel<<<dim3(ML, NB), ND / 4>>>(hidden, acoustic, ML);
}

// round 15
// speedup vs baseline: 1.0134x; 1.0134x over previous
#include <cuda_runtime.h>
#include <cstdint>

#define NB 16
#define NT 2048
#define ND 512
#define TBLK 8             // timesteps per alphas block
#define CH 32              // pass-2 chunk length (timesteps)
#define NCH (NT / CH)      // 64 chunks

// ---------------- scratch (device globals; no allocation allowed) ----------
__device__ __align__(16) float g_aT4[NT * NB];   // alphas, layout [t/4][b][4]
__device__ __align__(16) float g_Wt[NB * NT];    // per-step weight (cur), exact
__device__ __align__(16) float2 g_fire[NB * NT]; // per fire: (t as int bits, rem)
__device__ float g_integ0[NCH * NB];             // integ at chunk start
__device__ int   g_nf0[NCH * NB];                // fire count before chunk
__device__ int   g_nf[NB];                       // total fire count per batch

// set.ge.f32 -> 1.0f/0.0f without a predicate on the dependency chain
__device__ __forceinline__ float fset_ge1(float s) {
    float r;
    asm("set.ge.f32.f32 %0, %1, 0f3F800000;" : "=f"(r) : "f"(s));
    return r;
}

__device__ __forceinline__ uint32_t smem_u32(const void* p) {
    uint32_t a;
    asm("{ .reg .u64 t; cvta.to.shared.u64 t, %1; cvt.u32.u64 %0, t; }"
        : "=r"(a) : "l"(p));
    return a;
}

__device__ __forceinline__ void mbar_wait0(uint32_t mbar) {
    asm volatile(
        "{\n\t.reg .pred P1;\n\t"
        "W%=:\n\t"
        "mbarrier.try_wait.parity.acquire.cta.shared::cta.b64 P1, [%0], 0, 0x989680;\n\t"
        "@!P1 bra W%=;\n\t}"
        :: "r"(mbar) : "memory");
}

// ---------------- kernel A: alphas (r13-proven, byte-identical) -------------
// 128 threads cover 8 consecutive t of one batch; thread handles the FIXED
// d-slice d = tid*4 for all 8 t. TMA fills rows t0-1..t0+8 (20KB smem);
// weights preload while the TMA is in flight. Occupancy 8.
__global__ __launch_bounds__(128, 8)
void alphas_kernel(const float* __restrict__ hidden,
                   const float* __restrict__ conv_w,
                   const float* __restrict__ conv_b,
                   const float* __restrict__ lin_w,
                   const float* __restrict__ lin_b,
                   float* __restrict__ alphas) {
    __shared__ __align__(128) float sh[(TBLK + 2) * ND];   // 20KB
    __shared__ __align__(8) unsigned long long mbar;
    __shared__ float red[4][TBLK];

    const int b  = blockIdx.y;
    const int t0 = blockIdx.x * TBLK;

    const int gstart = (t0 == 0) ? 0 : t0 - 1;
    const int gend   = (t0 + TBLK < NT) ? t0 + TBLK : NT - 1;
    const int nrows  = gend - gstart + 1;           // 9 or 10
    const int dstrow = (t0 == 0) ? 1 : 0;

    const uint32_t mb = smem_u32(&mbar);
    if (threadIdx.x == 0) {
        asm volatile("mbarrier.init.shared.b64 [%0], 1;" :: "r"(mb) : "memory");
        const uint32_t bytes = nrows * ND * 4;
        const uint32_t dst   = smem_u32(sh) + dstrow * ND * 4;
        const float* src = hidden + (size_t)b * NT * ND + (size_t)gstart * ND;
        asm volatile("mbarrier.arrive.expect_tx.shared.b64 _, [%0], %1;"
                     :: "r"(mb), "r"(bytes) : "memory");
        asm volatile(
            "cp.async.bulk.shared::cta.global.mbarrier::complete_tx::bytes "
            "[%0], [%1], %2, [%3];"
            :: "r"(dst), "l"(src), "r"(bytes), "r"(mb) : "memory");
    }

    // weight preload — overlaps the TMA flight
    const int d = threadIdx.x * 4;
    const float4 c0 = *reinterpret_cast<const float4*>(&conv_w[d * 3]);
    const float4 c1 = *reinterpret_cast<const float4*>(&conv_w[d * 3 + 4]);
    const float4 c2 = *reinterpret_cast<const float4*>(&conv_w[d * 3 + 8]);
    const float4 w0 = make_float4(c0.x, c0.w, c1.z, c2.y);
    const float4 w1 = make_float4(c0.y + 1.f, c1.x + 1.f, c1.w + 1.f, c2.z + 1.f);
    const float4 w2 = make_float4(c0.z, c1.y, c2.x, c2.w);
    const float4 cb4 = *reinterpret_cast<const float4*>(&conv_b[d]);
    const float4 lw  = *reinterpret_cast<const float4*>(&lin_w[d]);
    const float lb   = __ldg(lin_b);

    if (t0 == 0) {
        *reinterpret_cast<float4*>(&sh[d]) = make_float4(0.f, 0.f, 0.f, 0.f);
    } else if (t0 + TBLK == NT) {
        *reinterpret_cast<float4*>(&sh[(TBLK + 1) * ND + d]) =
            make_float4(0.f, 0.f, 0.f, 0.f);
    }

    __syncthreads();        // publish mbar init (and pad rows)
    mbar_wait0(mb);

    // rolling 3-tap window over 8 timesteps, fixed d-slice
    float acc[TBLK];
    float4 hm = *reinterpret_cast<const float4*>(&sh[d]);
    float4 hc = *reinterpret_cast<const float4*>(&sh[ND + d]);
#pragma unroll
    for (int i = 0; i < TBLK; i++) {
        const float4 hp = *reinterpret_cast<const float4*>(&sh[(i + 2) * ND + d]);
        float a = 0.f, v;
        v = fmaf(hm.x, w0.x, fmaf(hc.x, w1.x, fmaf(hp.x, w2.x, cb4.x)));
        a = fmaf(fmaxf(v, 0.f), lw.x, a);
        v = fmaf(hm.y, w0.y, fmaf(hc.y, w1.y, fmaf(hp.y, w2.y, cb4.y)));
        a = fmaf(fmaxf(v, 0.f), lw.y, a);
        v = fmaf(hm.z, w0.z, fmaf(hc.z, w1.z, fmaf(hp.z, w2.z, cb4.z)));
        a = fmaf(fmaxf(v, 0.f), lw.z, a);
        v = fmaf(hm.w, w0.w, fmaf(hc.w, w1.w, fmaf(hp.w, w2.w, cb4.w)));
        a = fmaf(fmaxf(v, 0.f), lw.w, a);
        acc[i] = a;
        hm = hc; hc = hp;
    }

    // in-warp butterfly (8 independent chains pipeline the SHFL latency)
#pragma unroll
    for (int o = 16; o > 0; o >>= 1) {
#pragma unroll
        for (int i = 0; i < TBLK; i++)
            acc[i] += __shfl_xor_sync(0xffffffffu, acc[i], o);
    }
    const int warp = threadIdx.x >> 5;
    if ((threadIdx.x & 31) == 0) {
#pragma unroll
        for (int i = 0; i < TBLK; i++) red[warp][i] = acc[i];
    }
    __syncthreads();

    if (threadIdx.x < TBLK) {
        const int i = threadIdx.x;
        const float s = ((red[0][i] + red[1][i]) + (red[2][i] + red[3][i])) + lb;
        const float sg = 1.0f / (1.0f + __expf(-s));
        const int t = t0 + i;
        alphas[b * NT + t] = sg;
        g_aT4[((t >> 2) * NB + b) * 4 + (t & 3)] = sg;
    }
}

// ---------------- kernel B1: minimal sequential chain (pass 1) -------------
// (r7/r11-proven) Chain: FADD -> FSET (predicate-free) -> FADD = 12 cyc/step.
__global__ void scan_pass1(float* __restrict__ token_num) {
    const int b = threadIdx.x;
    if (b >= NB) return;

    const float4* ap = reinterpret_cast<const float4*>(g_aT4) + b;
    float4 buf_cur[8], buf_nxt[8];
#pragma unroll
    for (int k = 0; k < 8; k++) buf_cur[k] = ap[k * NB];

    float integ = 0.f, tn = 0.f, nfF = 0.f;

    for (int t0 = 0; t0 < NT; t0 += CH) {
        g_integ0[(t0 >> 5) * NB + b] = integ;
        g_nf0[(t0 >> 5) * NB + b]   = (int)nfF;
        if (t0 + CH < NT) {
#pragma unroll
            for (int k = 0; k < 8; k++) buf_nxt[k] = ap[((t0 >> 2) + 8 + k) * NB];
        }
#pragma unroll
        for (int k = 0; k < 8; k++) {
            float a4[4] = {buf_cur[k].x, buf_cur[k].y, buf_cur[k].z, buf_cur[k].w};
#pragma unroll
            for (int i = 0; i < 4; i++) {
                const float a   = a4[i];
                const float s   = integ + a;     // chain: FADD
                const float sel = fset_ge1(s);   // chain: FSET (1.0/0.0, no pred)
                nfF += sel;                      // off-chain
                tn  += a;                        // off-chain
                integ = s - sel;                 // chain: FADD (== s-1.0f at fires)
            }
        }
#pragma unroll
        for (int k = 0; k < 8; k++) buf_cur[k] = buf_nxt[k];
    }
    g_nf[b] = (int)nfF;
    token_num[b] = tn;
}

// ---------------- kernel B2: parallel chunk replay (pass 2) ----------------
__global__ void scan_pass2(float* __restrict__ fires) {
    const int c = blockIdx.x;
    const int b = threadIdx.x;
    if (b >= NB) return;

    float integ = g_integ0[c * NB + b];
    int nf      = g_nf0[c * NB + b];
    const int tbase = c * CH;
    const float4* ap = reinterpret_cast<const float4*>(g_aT4) + b;
    float*  fb = fires + b * NT;
    float*  wb = g_Wt + b * NT;
    float2* pb = g_fire + b * NT;

#pragma unroll
    for (int k = 0; k < 8; k++) {
        const float4 av = ap[((tbase >> 2) + k) * NB];
        float a4[4] = {av.x, av.y, av.z, av.w};
        float4 fout, wout;
#pragma unroll
        for (int i = 0; i < 4; i++) {
            const float a    = a4[i];
            const float dist = 1.0f - integ;
            const float s    = integ + a;
            const bool fire  = (s >= 1.0f);
            const float cur  = fire ? dist : a;
            ((float*)&fout)[i] = s;
            ((float*)&wout)[i] = cur;
            const float rem = a - cur;
            if (fire) pb[nf] = make_float2(__int_as_float(tbase + k * 4 + i), rem);
            nf += fire ? 1 : 0;
            integ = fire ? (s - 1.0f) : s;
        }
        const int t = tbase + k * 4;
        *reinterpret_cast<float4*>(fb + t) = fout;
        *reinterpret_cast<float4*>(wb + t) = wout;
    }
}

// ---------------- kernel C: rank-PAIR gather, hot-first ---------------------
// Block handles ranks (2g, 2g+1), pairs scheduled hot-first. Rank 2g runs the
// r13 loop exactly; rank 2g+1 seeds from the fire row of rank 2g, which is
// still in REGISTERS (r13 reloaded it from L2). Same row data, same float
// ops, same order => bit-exact. Saves one seed-row load + one fire-record
// round-trip per pair (~15% of gather traffic).
__global__ __launch_bounds__(128)
void gather_kernel(const float* __restrict__ hidden,
                   float* __restrict__ acoustic, int ML) {
    const int g  = gridDim.x - 1 - blockIdx.x;      // hot pairs first
    const int r0 = g * 2;
    const int b  = blockIdx.y;
    const int d  = threadIdx.x * 4;
    const int nf = g_nf[b];

    const float*  hb = hidden + (size_t)b * NT * ND + d;
    const float*  wb = g_Wt + b * NT;
    const float2* fr = g_fire + b * NT;
    float* ob = acoustic + ((size_t)b * ML + r0) * ND + d;

    const float4 z = make_float4(0.f, 0.f, 0.f, 0.f);
    float4 out0 = z, out1 = z;

    if (r0 < nf) {
        // fire records for the pair (and predecessor), fetched in parallel
        const float2 fp = fr[r0 > 0 ? r0 - 1 : 0];
        const float2 f0 = fr[r0];
        const float2 f1 = fr[r0 + 1 < nf ? r0 + 1 : r0];
        const int end0  = __float_as_int(f0.x);

        float4 acc = z;
        int start = 0;
        if (r0 > 0) {
            const int ps    = __float_as_int(fp.x);
            const float rem = fp.y;
            const float4 h  = *reinterpret_cast<const float4*>(hb + (size_t)ps * ND);
            acc.x = rem * h.x; acc.y = rem * h.y;
            acc.z = rem * h.z; acc.w = rem * h.w;
            start = ps + 1;
        }
        float4 lasth = z;
        for (int t = start; t <= end0; t++) {
            const float w  = wb[t];
            const float4 h = *reinterpret_cast<const float4*>(hb + (size_t)t * ND);
            acc.x = fmaf(w, h.x, acc.x); acc.y = fmaf(w, h.y, acc.y);
            acc.z = fmaf(w, h.z, acc.z); acc.w = fmaf(w, h.w, acc.w);
            lasth = h;
        }
        out0 = acc;

        if (r0 + 1 < nf) {
            // seed rank r0+1 from the fire row of r0 (register reuse)
            acc.x = f0.y * lasth.x; acc.y = f0.y * lasth.y;
            acc.z = f0.y * lasth.z; acc.w = f0.y * lasth.w;
            const int end1 = __float_as_int(f1.x);
            for (int t = end0 + 1; t <= end1; t++) {
                const float w  = wb[t];
                const float4 h = *reinterpret_cast<const float4*>(hb + (size_t)t * ND);
                acc.x = fmaf(w, h.x, acc.x); acc.y = fmaf(w, h.y, acc.y);
                acc.z = fmaf(w, h.z, acc.z); acc.w = fmaf(w, h.w, acc.w);
            }
            out1 = acc;
        }
    }

    // stores (zeros for r >= nf — reference zero-pads; overwrites 0xAA poison)
    *reinterpret_cast<float4*>(ob) = out0;
    if (r0 + 1 < ML)
        *reinterpret_cast<float4*>(ob + ND) = out1;
}

// ---------------- launch ----------------------------------------------------
extern "C" void kernel_launch(void* const* d_in, const int* in_sizes, int n_in,
                              void* d_out, int out_size) {
    const float* hidden = (const float*)d_in[0];
    const float* conv_w = (const float*)d_in[1];
    const float* conv_b = (const float*)d_in[2];
    const float* lin_w  = (const float*)d_in[3];
    const float* lin_b  = (const float*)d_in[4];
    float* out = (float*)d_out;

    // out = concat(acoustic[B,ML,D], token_num[B], alphas[B,T], fires[B,T])
    const int ML = (out_size - NB - 2 * NB * NT) / (NB * ND);
    float* acoustic  = out;
    float* token_num = out + (size_t)NB * ML * ND;
    float* alphas    = token_num + NB;
    float* fires     = alphas + NB * NT;

    alphas_kernel<<<dim3(NT / TBLK, NB), 128>>>(hidden, conv_w, conv_b,
                                                lin_w, lin_b, alphas);
    scan_pass1<<<1, 32>>>(token_num);
    scan_pass2<<<NCH, 32>>>(fires);
    if (ML > 0)
        gather_kernel<<<dim3((ML + 1) / 2, NB), ND / 4>>>(hidden, acoustic, ML);
}

// round 16
// speedup vs baseline: 1.0449x; 1.0311x over previous
#include <cuda_runtime.h>
#include <cstdint>

#define NB 16
#define NT 2048
#define ND 512
#define TBLK 8             // timesteps per alphas block
#define CH 32              // pass-2 chunk length (timesteps)
#define NCH (NT / CH)      // 64 chunks

// ---------------- scratch (device globals; no allocation allowed) ----------
__device__ __align__(16) float g_aT4[NT * NB];   // alphas, layout [t/4][b][4]
__device__ __align__(16) float g_Wt[NB * NT];    // per-step weight (cur), exact
__device__ __align__(16) float2 g_fire[NB * NT]; // per fire: (t as int bits, rem)
__device__ float g_integ0[NCH * NB];             // integ at chunk start
__device__ int   g_nf0[NCH * NB];                // fire count before chunk
__device__ int   g_nf[NB];                       // total fire count per batch

// set.ge.f32 -> 1.0f/0.0f without a predicate on the dependency chain
__device__ __forceinline__ float fset_ge1(float s) {
    float r;
    asm("set.ge.f32.f32 %0, %1, 0f3F800000;" : "=f"(r) : "f"(s));
    return r;
}

__device__ __forceinline__ uint32_t smem_u32(const void* p) {
    uint32_t a;
    asm("{ .reg .u64 t; cvta.to.shared.u64 t, %1; cvt.u32.u64 %0, t; }"
        : "=r"(a) : "l"(p));
    return a;
}

__device__ __forceinline__ void mbar_wait0(uint32_t mbar) {
    asm volatile(
        "{\n\t.reg .pred P1;\n\t"
        "W%=:\n\t"
        "mbarrier.try_wait.parity.acquire.cta.shared::cta.b64 P1, [%0], 0, 0x989680;\n\t"
        "@!P1 bra W%=;\n\t}"
        :: "r"(mbar) : "memory");
}

// ---------------- kernel A: alphas (r13-proven, byte-identical) -------------
// 128 threads cover 8 consecutive t of one batch; thread handles the FIXED
// d-slice d = tid*4 for all 8 t. TMA fills rows t0-1..t0+8 (20KB smem);
// weights preload while the TMA is in flight. Occupancy 8.
__global__ __launch_bounds__(128, 8)
void alphas_kernel(const float* __restrict__ hidden,
                   const float* __restrict__ conv_w,
                   const float* __restrict__ conv_b,
                   const float* __restrict__ lin_w,
                   const float* __restrict__ lin_b,
                   float* __restrict__ alphas) {
    __shared__ __align__(128) float sh[(TBLK + 2) * ND];   // 20KB
    __shared__ __align__(8) unsigned long long mbar;
    __shared__ float red[4][TBLK];

    const int b  = blockIdx.y;
    const int t0 = blockIdx.x * TBLK;

    const int gstart = (t0 == 0) ? 0 : t0 - 1;
    const int gend   = (t0 + TBLK < NT) ? t0 + TBLK : NT - 1;
    const int nrows  = gend - gstart + 1;           // 9 or 10
    const int dstrow = (t0 == 0) ? 1 : 0;

    const uint32_t mb = smem_u32(&mbar);
    if (threadIdx.x == 0) {
        asm volatile("mbarrier.init.shared.b64 [%0], 1;" :: "r"(mb) : "memory");
        const uint32_t bytes = nrows * ND * 4;
        const uint32_t dst   = smem_u32(sh) + dstrow * ND * 4;
        const float* src = hidden + (size_t)b * NT * ND + (size_t)gstart * ND;
        asm volatile("mbarrier.arrive.expect_tx.shared.b64 _, [%0], %1;"
                     :: "r"(mb), "r"(bytes) : "memory");
        asm volatile(
            "cp.async.bulk.shared::cta.global.mbarrier::complete_tx::bytes "
            "[%0], [%1], %2, [%3];"
            :: "r"(dst), "l"(src), "r"(bytes), "r"(mb) : "memory");
    }

    // weight preload — overlaps the TMA flight
    const int d = threadIdx.x * 4;
    const float4 c0 = *reinterpret_cast<const float4*>(&conv_w[d * 3]);
    const float4 c1 = *reinterpret_cast<const float4*>(&conv_w[d * 3 + 4]);
    const float4 c2 = *reinterpret_cast<const float4*>(&conv_w[d * 3 + 8]);
    const float4 w0 = make_float4(c0.x, c0.w, c1.z, c2.y);
    const float4 w1 = make_float4(c0.y + 1.f, c1.x + 1.f, c1.w + 1.f, c2.z + 1.f);
    const float4 w2 = make_float4(c0.z, c1.y, c2.x, c2.w);
    const float4 cb4 = *reinterpret_cast<const float4*>(&conv_b[d]);
    const float4 lw  = *reinterpret_cast<const float4*>(&lin_w[d]);
    const float lb   = __ldg(lin_b);

    if (t0 == 0) {
        *reinterpret_cast<float4*>(&sh[d]) = make_float4(0.f, 0.f, 0.f, 0.f);
    } else if (t0 + TBLK == NT) {
        *reinterpret_cast<float4*>(&sh[(TBLK + 1) * ND + d]) =
            make_float4(0.f, 0.f, 0.f, 0.f);
    }

    __syncthreads();        // publish mbar init (and pad rows)
    mbar_wait0(mb);

    // rolling 3-tap window over 8 timesteps, fixed d-slice
    float acc[TBLK];
    float4 hm = *reinterpret_cast<const float4*>(&sh[d]);
    float4 hc = *reinterpret_cast<const float4*>(&sh[ND + d]);
#pragma unroll
    for (int i = 0; i < TBLK; i++) {
        const float4 hp = *reinterpret_cast<const float4*>(&sh[(i + 2) * ND + d]);
        float a = 0.f, v;
        v = fmaf(hm.x, w0.x, fmaf(hc.x, w1.x, fmaf(hp.x, w2.x, cb4.x)));
        a = fmaf(fmaxf(v, 0.f), lw.x, a);
        v = fmaf(hm.y, w0.y, fmaf(hc.y, w1.y, fmaf(hp.y, w2.y, cb4.y)));
        a = fmaf(fmaxf(v, 0.f), lw.y, a);
        v = fmaf(hm.z, w0.z, fmaf(hc.z, w1.z, fmaf(hp.z, w2.z, cb4.z)));
        a = fmaf(fmaxf(v, 0.f), lw.z, a);
        v = fmaf(hm.w, w0.w, fmaf(hc.w, w1.w, fmaf(hp.w, w2.w, cb4.w)));
        a = fmaf(fmaxf(v, 0.f), lw.w, a);
        acc[i] = a;
        hm = hc; hc = hp;
    }

    // in-warp butterfly (8 independent chains pipeline the SHFL latency)
#pragma unroll
    for (int o = 16; o > 0; o >>= 1) {
#pragma unroll
        for (int i = 0; i < TBLK; i++)
            acc[i] += __shfl_xor_sync(0xffffffffu, acc[i], o);
    }
    const int warp = threadIdx.x >> 5;
    if ((threadIdx.x & 31) == 0) {
#pragma unroll
        for (int i = 0; i < TBLK; i++) red[warp][i] = acc[i];
    }
    __syncthreads();

    if (threadIdx.x < TBLK) {
        const int i = threadIdx.x;
        const float s = ((red[0][i] + red[1][i]) + (red[2][i] + red[3][i])) + lb;
        const float sg = 1.0f / (1.0f + __expf(-s));
        const int t = t0 + i;
        alphas[b * NT + t] = sg;
        g_aT4[((t >> 2) * NB + b) * 4 + (t & 3)] = sg;
    }
}

// ---------------- kernel B1: minimal sequential chain (pass 1, PDL) --------
// (r7/r11-proven) Chain: FADD -> FSET (predicate-free) -> FADD = 12 cyc/step.
__global__ void scan_pass1(float* __restrict__ token_num) {
    cudaGridDependencySynchronize();    // PDL: wait for alphas' g_aT4
    const int b = threadIdx.x;
    if (b >= NB) return;

    const float4* ap = reinterpret_cast<const float4*>(g_aT4) + b;
    float4 buf_cur[8], buf_nxt[8];
#pragma unroll
    for (int k = 0; k < 8; k++) buf_cur[k] = ap[k * NB];

    float integ = 0.f, tn = 0.f, nfF = 0.f;

    for (int t0 = 0; t0 < NT; t0 += CH) {
        g_integ0[(t0 >> 5) * NB + b] = integ;
        g_nf0[(t0 >> 5) * NB + b]   = (int)nfF;
        if (t0 + CH < NT) {
#pragma unroll
            for (int k = 0; k < 8; k++) buf_nxt[k] = ap[((t0 >> 2) + 8 + k) * NB];
        }
#pragma unroll
        for (int k = 0; k < 8; k++) {
            float a4[4] = {buf_cur[k].x, buf_cur[k].y, buf_cur[k].z, buf_cur[k].w};
#pragma unroll
            for (int i = 0; i < 4; i++) {
                const float a   = a4[i];
                const float s   = integ + a;     // chain: FADD
                const float sel = fset_ge1(s);   // chain: FSET (1.0/0.0, no pred)
                nfF += sel;                      // off-chain
                tn  += a;                        // off-chain
                integ = s - sel;                 // chain: FADD (== s-1.0f at fires)
            }
        }
#pragma unroll
        for (int k = 0; k < 8; k++) buf_cur[k] = buf_nxt[k];
    }
    g_nf[b] = (int)nfF;
    token_num[b] = tn;
}

// ---------------- kernel B2: parallel chunk replay (pass 2, PDL) -----------
__global__ void scan_pass2(float* __restrict__ fires) {
    cudaGridDependencySynchronize();    // PDL: wait for pass1 snapshots
    const int c = blockIdx.x;
    const int b = threadIdx.x;
    if (b >= NB) return;

    float integ = g_integ0[c * NB + b];
    int nf      = g_nf0[c * NB + b];
    const int tbase = c * CH;
    const float4* ap = reinterpret_cast<const float4*>(g_aT4) + b;
    float*  fb = fires + b * NT;
    float*  wb = g_Wt + b * NT;
    float2* pb = g_fire + b * NT;

#pragma unroll
    for (int k = 0; k < 8; k++) {
        const float4 av = ap[((tbase >> 2) + k) * NB];
        float a4[4] = {av.x, av.y, av.z, av.w};
        float4 fout, wout;
#pragma unroll
        for (int i = 0; i < 4; i++) {
            const float a    = a4[i];
            const float dist = 1.0f - integ;
            const float s    = integ + a;
            const bool fire  = (s >= 1.0f);
            const float cur  = fire ? dist : a;
            ((float*)&fout)[i] = s;
            ((float*)&wout)[i] = cur;
            const float rem = a - cur;
            if (fire) pb[nf] = make_float2(__int_as_float(tbase + k * 4 + i), rem);
            nf += fire ? 1 : 0;
            integ = fire ? (s - 1.0f) : s;
        }
        const int t = tbase + k * 4;
        *reinterpret_cast<float4*>(fb + t) = fout;
        *reinterpret_cast<float4*>(wb + t) = wout;
    }
}

// ---------------- kernel C: segmented gather, hot-first, flat prologue -----
// r = ML-1-bid (hot rows first). g_nf + both fire records load UNCONDITIONALLY
// in parallel (clamped indices) — dependent-load chain depth 3 -> 2. Values
// consumed under identical conditions => bit-exact vs r13.
__global__ void gather_kernel(const float* __restrict__ hidden,
                              float* __restrict__ acoustic, int ML) {
    cudaGridDependencySynchronize();    // PDL: wait for pass2 outputs
    const int r = gridDim.x - 1 - blockIdx.x;       // hot rows first
    const int b = blockIdx.y;
    const int d = threadIdx.x * 4;

    // flat prologue: all three loads issue in parallel
    const int   nf = g_nf[b];
    const float2 fc = g_fire[b * NT + (r < NT ? r : NT - 1)];
    const float2 fp = g_fire[b * NT + (r > 0 ? r - 1 : 0)];

    float4 acc = make_float4(0.f, 0.f, 0.f, 0.f);
    if (r < nf) {
        const float* hb = hidden + (size_t)b * NT * ND + d;
        const int end   = __float_as_int(fc.x);
        int start = 0;
        if (r > 0) {
            const int ps    = __float_as_int(fp.x);
            const float rem = fp.y;
            const float4 h  = *reinterpret_cast<const float4*>(hb + (size_t)ps * ND);
            acc.x = rem * h.x; acc.y = rem * h.y;
            acc.z = rem * h.z; acc.w = rem * h.w;
            start = ps + 1;
        }
        for (int t = start; t <= end; t++) {
            const float w  = g_Wt[b * NT + t];   // uniform broadcast load (exact cur)
            const float4 h = *reinterpret_cast<const float4*>(hb + (size_t)t * ND);
            acc.x = fmaf(w, h.x, acc.x); acc.y = fmaf(w, h.y, acc.y);
            acc.z = fmaf(w, h.z, acc.z); acc.w = fmaf(w, h.w, acc.w);
        }
    }
    // r >= nf -> zeros (reference zero-pads); also overwrites 0xAA poison.
    *reinterpret_cast<float4*>(&acoustic[((size_t)b * ML + r) * ND + d]) = acc;
}

// ---------------- launch: PDL-chained pipeline -------------------------------
extern "C" void kernel_launch(void* const* d_in, const int* in_sizes, int n_in,
                              void* d_out, int out_size) {
    const float* hidden = (const float*)d_in[0];
    const float* conv_w = (const float*)d_in[1];
    const float* conv_b = (const float*)d_in[2];
    const float* lin_w  = (const float*)d_in[3];
    const float* lin_b  = (const float*)d_in[4];
    float* out = (float*)d_out;

    // out = concat(acoustic[B,ML,D], token_num[B], alphas[B,T], fires[B,T])
    const int ML = (out_size - NB - 2 * NB * NT) / (NB * ND);
    float* acoustic  = out;
    float* token_num = out + (size_t)NB * ML * ND;
    float* alphas    = token_num + NB;
    float* fires     = alphas + NB * NT;

    alphas_kernel<<<dim3(NT / TBLK, NB), 128>>>(hidden, conv_w, conv_b,
                                                lin_w, lin_b, alphas);

    // PDL attribute: dependent kernel's prologue overlaps predecessor epilogue
    cudaLaunchAttribute attrs[1];
    attrs[0].id = cudaLaunchAttributeProgrammaticStreamSerialization;
    attrs[0].val.programmaticStreamSerializationAllowed = 1;

    {
        cudaLaunchConfig_t cfg = {};
        cfg.gridDim = dim3(1, 1, 1);
        cfg.blockDim = dim3(32, 1, 1);
        cfg.attrs = attrs; cfg.numAttrs = 1;
        cudaLaunchKernelEx(&cfg, scan_pass1, token_num);
    }
    {
        cudaLaunchConfig_t cfg = {};
        cfg.gridDim = dim3(NCH, 1, 1);
        cfg.blockDim = dim3(32, 1, 1);
        cfg.attrs = attrs; cfg.numAttrs = 1;
        cudaLaunchKernelEx(&cfg, scan_pass2, fires);
    }
    if (ML > 0) {
        cudaLaunchConfig_t cfg = {};
        cfg.gridDim = dim3(ML, NB, 1);
        cfg.blockDim = dim3(ND / 4, 1, 1);
        cfg.attrs = attrs; cfg.numAttrs = 1;
        cudaLaunchKernelEx(&cfg, gather_kernel, hidden, acoustic, ML);
    }
}